// round 16
// baseline (speedup 1.0000x reference)
#include <cuda_runtime.h>
#include <cstdint>

#define B_ROWS 32768
#define C_COLS 1000
#define C_PAD  1024
#define F_DIM  256

#define BM      32      // feature rows per CTA
#define BNC     256     // proto cols per chunk
#define NCHUNK  4       // 1024 / 256
#define THREADS 512     // 16 warps

// SMEM layout (bytes)
#define SM_A      0                       // 32 rows x 256B (swizzled int8) = 8KB
#define SM_SAINV  8192                    // 32 floats: feature dequant scales
#define SM_SROW   8320                    // 32 floats: row sums
#define SM_RB     8448                    // 1024 floats: proto dequant scales
#define SM_B0     12800                   // proto chunk: 256 x 256B = 64KB
#define SM_B1     (12800 + 65536)
#define SM_B2     (12800 + 131072)
#define SM_TOTAL  (12800 + 196608)        // 209408 <= 227KB

// Scratch (device globals — no allocation allowed)
__device__ __align__(16) int8_t g_Pq[(size_t)C_PAD * F_DIM];
__device__ float g_Pscale[C_PAD];

// ---------------------------------------------------------------------------
// helpers
// ---------------------------------------------------------------------------
__device__ __forceinline__ uint32_t smem_u32(const void* p) {
    uint32_t a;
    asm("{ .reg .u64 t; cvta.to.shared.u64 t, %1; cvt.u32.u64 %0, t; }" : "=r"(a) : "l"(p));
    return a;
}
__device__ __forceinline__ void ldsm_x4(uint32_t* r, uint32_t addr) {
    asm volatile("ldmatrix.sync.aligned.m8n8.x4.shared.b16 {%0,%1,%2,%3}, [%4];\n"
        : "=r"(r[0]), "=r"(r[1]), "=r"(r[2]), "=r"(r[3]) : "r"(addr));
}
__device__ __forceinline__ void mma16832s8(int* c, const uint32_t* a, uint32_t b0, uint32_t b1) {
    asm volatile(
        "mma.sync.aligned.m16n8k32.row.col.s32.s8.s8.s32 "
        "{%0,%1,%2,%3}, {%4,%5,%6,%7}, {%8,%9}, {%0,%1,%2,%3};\n"
        : "+r"(c[0]), "+r"(c[1]), "+r"(c[2]), "+r"(c[3])
        : "r"(a[0]), "r"(a[1]), "r"(a[2]), "r"(a[3]), "r"(b0), "r"(b1));
}
__device__ __forceinline__ float fsqrt_ap(float x) {
    float r; asm("sqrt.approx.f32 %0, %1;" : "=f"(r) : "f"(x)); return r;
}
__device__ __forceinline__ uint32_t pack4(float x0, float x1, float x2, float x3, float qs) {
    int q0 = __float2int_rn(x0 * qs), q1 = __float2int_rn(x1 * qs);
    int q2 = __float2int_rn(x2 * qs), q3 = __float2int_rn(x3 * qs);
    return (q0 & 255) | ((q1 & 255) << 8) | ((q2 & 255) << 16) | ((q3 & 255) << 24);
}
// 16B-chunk swizzle within a 256B row (16 chunks; XOR low 3 bits by row&7)
__device__ __forceinline__ uint32_t sw16(int c, int r) {
    return (uint32_t)(((c & 7) ^ (r & 7)) | (c & 8));
}
#define CP_ASYNC16(dst, src) \
    asm volatile("cp.async.cg.shared.global [%0], [%1], 16;" :: "r"(dst), "l"(src))
#define CP_COMMIT() asm volatile("cp.async.commit_group;" ::: "memory")
#define CP_WAIT0()  asm volatile("cp.async.wait_group 0;" ::: "memory")
#define CP_WAIT1()  asm volatile("cp.async.wait_group 1;" ::: "memory")
#define CP_WAIT2()  asm volatile("cp.async.wait_group 2;" ::: "memory")

// ---------------------------------------------------------------------------
// Kernel 1: L2-normalize prototypes -> per-row-scaled int8 + dequant scale.
// q[row][k] = round(x_k * 126 / max|x|);  g_Pscale[row] = max|x| / (126*||x||)
// Rows [1000,1024): zeros, scale 0 (forces cos=0 on padding).
// ---------------------------------------------------------------------------
__global__ void norm_protos_kernel(const float* __restrict__ proto) {
    int gtid = blockIdx.x * blockDim.x + threadIdx.x;
    int row  = gtid >> 5;
    int lane = gtid & 31;
    if (row >= C_PAD) return;

    if (row >= C_COLS) {
        uint2 z = {0u, 0u};
        reinterpret_cast<uint2*>(g_Pq)[row * 32 + lane] = z;
        if (lane == 0) g_Pscale[row] = 0.0f;
        return;
    }
    const float4* src = reinterpret_cast<const float4*>(proto + (size_t)row * F_DIM);
    float4 v0 = src[lane * 2 + 0];
    float4 v1 = src[lane * 2 + 1];

    float ss = v0.x*v0.x + v0.y*v0.y + v0.z*v0.z + v0.w*v0.w
             + v1.x*v1.x + v1.y*v1.y + v1.z*v1.z + v1.w*v1.w;
    float mx = fmaxf(fmaxf(fmaxf(fabsf(v0.x), fabsf(v0.y)), fmaxf(fabsf(v0.z), fabsf(v0.w))),
                     fmaxf(fmaxf(fabsf(v1.x), fabsf(v1.y)), fmaxf(fabsf(v1.z), fabsf(v1.w))));
    #pragma unroll
    for (int o = 16; o; o >>= 1) {
        ss += __shfl_xor_sync(0xFFFFFFFFu, ss, o);
        mx  = fmaxf(mx, __shfl_xor_sync(0xFFFFFFFFu, mx, o));
    }
    mx = fmaxf(mx, 1e-30f);
    float inv = 1.0f / fmaxf(sqrtf(ss), 1e-12f);
    float qs  = 126.0f / mx;

    uint2 q;
    q.x = pack4(v0.x, v0.y, v0.z, v0.w, qs);
    q.y = pack4(v1.x, v1.y, v1.z, v1.w, qs);
    reinterpret_cast<uint2*>(g_Pq)[row * 32 + lane] = q;
    if (lane == 0) g_Pscale[row] = mx * inv * (1.0f / 126.0f);
}

// ---------------------------------------------------------------------------
// Kernel 2: fused normalize+quantize(A) + int8 GEMM + epilogue.
//   CTA: 32 feature rows x all 1024 protos.  IMMA m16n8k32 s8s8s32.
//   Warp w: mt=w&1 (16 rows), strip s=w>>1 (32 protos per 256-col chunk).
//   acc int[4 chunks][4 ntiles][4] = 64 regs; 4 independent chains per k-step.
//   A: quantized in-CTA from fp32 (per-row scale) into swizzled smem (8KB).
//   B: int8 chunks (256 protos x 256B = 64KB) via 3-deep cp.async ring.
//   Dequant in epilogue: cos = d * sainv[row] * rb[col]; then iso/mean/write.
// ---------------------------------------------------------------------------
__global__ void __launch_bounds__(THREADS, 1)
fused_gemm_kernel(const float* __restrict__ feat,
                  const float* __restrict__ dscale, const float* __restrict__ temp,
                  float* __restrict__ out) {
    extern __shared__ __align__(16) unsigned char smem[];
    const uint32_t smem_base = smem_u32(smem);

    const int tid  = threadIdx.x;
    const int lane = tid & 31;
    const int warp = tid >> 5;
    const int mt   = warp & 1;     // 0/1 -> rows 0-15 / 16-31
    const int s    = warp >> 1;    // 0..7: 32-proto strip within each 256-col chunk

    float* sainv = reinterpret_cast<float*>(smem + SM_SAINV);
    float* srow  = reinterpret_cast<float*>(smem + SM_SROW);
    float* rbs   = reinterpret_cast<float*>(smem + SM_RB);
    if (tid < BM) srow[tid] = 0.0f;

    const uint32_t bufs[3] = { smem_base + SM_B0, smem_base + SM_B1, smem_base + SM_B2 };
    const char* gBq = reinterpret_cast<const char*>(g_Pq);

    // ---- Preload B chunks 0,1,2 (+ proto scales with group 0) ----
    #pragma unroll
    for (int pj = 0; pj < 3; pj++) {
        #pragma unroll
        for (int it = 0; it < 8; it++) {
            int idx = it * THREADS + tid;            // 0..4095
            int r = idx >> 4, c = idx & 15;
            CP_ASYNC16(bufs[pj] + r * 256 + (sw16(c, r) << 4),
                       gBq + (size_t)(pj * BNC + r) * 256 + c * 16);
        }
        if (pj == 0 && tid < 256)
            CP_ASYNC16(smem_base + SM_RB + tid * 16, g_Pscale + tid * 4);
        CP_COMMIT();
    }

    // ---- Normalize + quantize A rows in-CTA: warp w -> rows 2w, 2w+1 ----
    {
        const float4* gF = reinterpret_cast<const float4*>(feat)
                         + (size_t)blockIdx.x * BM * (F_DIM / 4);
        #pragma unroll
        for (int rr = 0; rr < 2; rr++) {
            int r = warp * 2 + rr;
            float4 v0 = __ldg(&gF[r * 64 + lane * 2 + 0]);
            float4 v1 = __ldg(&gF[r * 64 + lane * 2 + 1]);
            float ss = v0.x*v0.x + v0.y*v0.y + v0.z*v0.z + v0.w*v0.w
                     + v1.x*v1.x + v1.y*v1.y + v1.z*v1.z + v1.w*v1.w;
            float mx = fmaxf(
                fmaxf(fmaxf(fabsf(v0.x), fabsf(v0.y)), fmaxf(fabsf(v0.z), fabsf(v0.w))),
                fmaxf(fmaxf(fabsf(v1.x), fabsf(v1.y)), fmaxf(fabsf(v1.z), fabsf(v1.w))));
            #pragma unroll
            for (int o = 16; o; o >>= 1) {
                ss += __shfl_xor_sync(0xFFFFFFFFu, ss, o);
                mx  = fmaxf(mx, __shfl_xor_sync(0xFFFFFFFFu, mx, o));
            }
            mx = fmaxf(mx, 1e-30f);
            float inv = 1.0f / fmaxf(sqrtf(ss), 1e-12f);
            float qs  = 126.0f / mx;

            uint2 q;
            q.x = pack4(v0.x, v0.y, v0.z, v0.w, qs);
            q.y = pack4(v1.x, v1.y, v1.z, v1.w, qs);
            // lane holds bytes [lane*8, lane*8+8): chunk c=lane>>1, half=lane&1
            int c = lane >> 1;
            uint32_t addr = smem_base + SM_A + r * 256 + (sw16(c, r) << 4) + (lane & 1) * 8;
            asm volatile("st.shared.v2.u32 [%0], {%1, %2};" :: "r"(addr), "r"(q.x), "r"(q.y));
            if (lane == 0) sainv[r] = mx * inv * (1.0f / 126.0f);
        }
    }
    CP_WAIT2();        // chunk 0 (+ scales) resident
    __syncthreads();

    // ---- ldsm lane addressing ----
    const int a_row = mt * 16 + (lane & 15);
    const int a_h   = lane >> 4;
    const uint32_t aBase = smem_base + SM_A + a_row * 256;
    const int aX = a_row & 7;

    const int b_n = (lane & 7) | ((lane & 16) >> 1);   // 0..15 within half-strip
    const int b_h = (lane >> 3) & 1;
    const int n0 = s * 32 + b_n;
    const int n1 = n0 + 16;
    const uint32_t bOff0 = (uint32_t)(n0 * 256);
    const uint32_t bOff1 = (uint32_t)(n1 * 256);
    const int bX0 = n0 & 7, bX1 = n1 & 7;

    int acc[NCHUNK][4][4];
    #pragma unroll
    for (int j = 0; j < NCHUNK; j++)
        #pragma unroll
        for (int t = 0; t < 4; t++)
            #pragma unroll
            for (int i = 0; i < 4; i++) acc[j][t][i] = 0;

    // ---- fragment double-buffer: preload (chunk 0, k=0) ----
    uint32_t afc[4], bfc[8], afn[4], bfn[8];
    ldsm_x4(afc, aBase + (sw16(a_h, a_row) << 4));
    ldsm_x4(bfc + 0, bufs[0] + bOff0 + (sw16(b_h, n0) << 4));
    ldsm_x4(bfc + 4, bufs[0] + bOff1 + (sw16(b_h, n1) << 4));

    // ---- Main loop: 4 chunks x 8 k32-steps ----
    #pragma unroll
    for (int j = 0; j < NCHUNK; j++) {
        const uint32_t bBase = bufs[j % 3];

        #pragma unroll
        for (int k = 0; k < 8; k++) {
            if (k < 7) {
                int ch = 2 * (k + 1);
                ldsm_x4(afn, aBase + (sw16(ch + a_h, a_row) << 4));
                ldsm_x4(bfn + 0, bBase + bOff0 + (sw16(ch + b_h, n0) << 4));
                ldsm_x4(bfn + 4, bBase + bOff1 + (sw16(ch + b_h, n1) << 4));
            }
            mma16832s8(acc[j][0], afc, bfc[0], bfc[1]);
            mma16832s8(acc[j][1], afc, bfc[2], bfc[3]);
            mma16832s8(acc[j][2], afc, bfc[4], bfc[5]);
            mma16832s8(acc[j][3], afc, bfc[6], bfc[7]);
            #pragma unroll
            for (int q = 0; q < 4; q++) afc[q] = afn[q];
            #pragma unroll
            for (int q = 0; q < 8; q++) bfc[q] = bfn[q];
        }

        if (j < NCHUNK - 1) {
            if (j < 2) CP_WAIT1(); else CP_WAIT0();
            __syncthreads();
            if (j == 0) {   // stream chunk 3 into buf 0
                #pragma unroll
                for (int it = 0; it < 8; it++) {
                    int idx = it * THREADS + tid;
                    int r = idx >> 4, c = idx & 15;
                    CP_ASYNC16(bufs[0] + r * 256 + (sw16(c, r) << 4),
                               gBq + (size_t)(3 * BNC + r) * 256 + c * 16);
                }
                CP_COMMIT();
            }
            uint32_t nb = bufs[(j + 1) % 3];
            ldsm_x4(afc, aBase + (sw16(a_h, a_row) << 4));
            ldsm_x4(bfc + 0, nb + bOff0 + (sw16(b_h, n0) << 4));
            ldsm_x4(bfc + 4, nb + bOff1 + (sw16(b_h, n1) << 4));
        }
    }

    // ---- Epilogue phase 1: dequant -> iso; masked row sums ----
    const float ads = fabsf(__ldg(dscale));
    const float it_ = 1.0f / __ldg(temp);
    const int tr = lane >> 2;            // 0..7
    const int tc = (lane & 3) * 2;       // 0,2,4,6
    const float sa0 = sainv[mt * 16 + tr];
    const float sa1 = sainv[mt * 16 + tr + 8];

    float iso[NCHUNK][4][4];
    float rs0 = 0.0f, rs1 = 0.0f;
    #pragma unroll
    for (int j = 0; j < NCHUNK; j++) {
        #pragma unroll
        for (int t = 0; t < 4; t++) {
            int cb = j * 256 + s * 32 + t * 8 + tc;
            float rb0 = rbs[cb], rb1 = rbs[cb + 1];
            float c0 = (float)acc[j][t][0] * (sa0 * rb0);
            float c1 = (float)acc[j][t][1] * (sa0 * rb1);
            float c2 = (float)acc[j][t][2] * (sa1 * rb0);
            float c3 = (float)acc[j][t][3] * (sa1 * rb1);
            float i0 = ads * fsqrt_ap(fmaxf(1.0f - c0, 0.0f));
            float i1 = ads * fsqrt_ap(fmaxf(1.0f - c1, 0.0f));
            float i2 = ads * fsqrt_ap(fmaxf(1.0f - c2, 0.0f));
            float i3 = ads * fsqrt_ap(fmaxf(1.0f - c3, 0.0f));
            iso[j][t][0] = i0; iso[j][t][1] = i1;
            iso[j][t][2] = i2; iso[j][t][3] = i3;
            if (cb < C_COLS) {            // cb even, C_COLS even: pair never straddles
                rs0 += i0 + i1;
                rs1 += i2 + i3;
            }
        }
    }
    rs0 += __shfl_xor_sync(0xFFFFFFFFu, rs0, 1);
    rs0 += __shfl_xor_sync(0xFFFFFFFFu, rs0, 2);
    rs1 += __shfl_xor_sync(0xFFFFFFFFu, rs1, 1);
    rs1 += __shfl_xor_sync(0xFFFFFFFFu, rs1, 2);
    if ((lane & 3) == 0) {
        atomicAdd(&srow[mt * 16 + tr], rs0);
        atomicAdd(&srow[mt * 16 + tr + 8], rs1);
    }
    __syncthreads();

    // ---- Epilogue phase 2: direct global float2 stores ----
    const float m0 = srow[mt * 16 + tr]     * (1.0f / (float)C_COLS);
    const float m1 = srow[mt * 16 + tr + 8] * (1.0f / (float)C_COLS);
    const size_t grow0 = (size_t)blockIdx.x * BM;
    float* out_r0 = out + (grow0 + mt * 16 + tr)     * C_COLS;
    float* out_r1 = out + (grow0 + mt * 16 + tr + 8) * C_COLS;

    #pragma unroll
    for (int j = 0; j < NCHUNK; j++) {
        #pragma unroll
        for (int t = 0; t < 4; t++) {
            int cb = j * 256 + s * 32 + t * 8 + tc;
            if (cb < C_COLS) {
                float2 w0 = { -(iso[j][t][0] + m0) * it_, -(iso[j][t][1] + m0) * it_ };
                float2 w1 = { -(iso[j][t][2] + m1) * it_, -(iso[j][t][3] + m1) * it_ };
                *reinterpret_cast<float2*>(out_r0 + cb) = w0;
                *reinterpret_cast<float2*>(out_r1 + cb) = w1;
            }
        }
    }
}

// ---------------------------------------------------------------------------
extern "C" void kernel_launch(void* const* d_in, const int* in_sizes, int n_in,
                              void* d_out, int out_size) {
    const float* feat  = (const float*)d_in[0];
    const float* proto = (const float*)d_in[1];
    const float* dsc   = (const float*)d_in[2];
    const float* temp  = (const float*)d_in[3];
    float* out = (float*)d_out;

    cudaFuncSetAttribute(fused_gemm_kernel,
                         cudaFuncAttributeMaxDynamicSharedMemorySize, SM_TOTAL);

    norm_protos_kernel<<<C_PAD / 8, 256>>>(proto);
    fused_gemm_kernel<<<B_ROWS / BM, THREADS, SM_TOTAL>>>(feat, dsc, temp, out);
}